// round 9
// baseline (speedup 1.0000x reference)
#include <cuda_runtime.h>
#include <cuda_fp16.h>
#include <cstdint>

// Problem constants
#define SLEN 512
#define BSZ  64
#define ID   512
#define HID  512
#define NG   2048   // 4*H
#define NBLK 128    // total persistent blocks for phase 2

#define HS_STRIDE 72                       // padded batch stride (halves)
#define CHUNK_BYTES (128 * HS_STRIDE * 2)  // one k-quarter = 18432 B

// Scratch (device globals: allocation-free)
static __device__ float    g_Xg[134217728];             // (D, S, B, 4H)
static __device__ __half   g_h[2][2][HID][HS_STRIDE];   // padded: src == smem layout
static __device__ unsigned g_flag[2][64];               // producer progress flags

__device__ __forceinline__ uint32_t smem_u32(const void* p) {
    uint32_t a;
    asm("{ .reg .u64 t; cvta.to.shared.u64 t, %1; cvt.u32.u64 %0, t; }"
        : "=r"(a) : "l"(p));
    return a;
}

// ===========================================================================
// Phase 1: Xg[d, r, :] = X[r,:] @ W[d]^T + Wb[d] + Rb[d]
// fp16 mma.sync.m16n8k16, fp32 accum (unchanged — proven).
// ===========================================================================
#define PSTR 40

__global__ __launch_bounds__(256) void gemm_xw_fp16(const float* __restrict__ X,
                                                    const float* __restrict__ W,
                                                    const float* __restrict__ Bb) {
    __shared__ __half As[128][PSTR];
    __shared__ __half Bs[128][PSTR];
    __shared__ float biass[128];

    const int tid  = threadIdx.x;
    const int wid  = tid >> 5, lane = tid & 31;
    const int d    = blockIdx.z;
    const int col0 = blockIdx.x * 128;
    const int row0 = blockIdx.y * 128;
    const float* Am = X + (size_t)row0 * ID;
    const float* Bm = W + ((size_t)d * NG + col0) * ID;
    float* C = g_Xg + (size_t)d * SLEN * BSZ * NG;

    if (blockIdx.x == 0 && blockIdx.y == 0 && blockIdx.z == 0 && tid < 128)
        g_flag[tid >> 6][tid & 63] = 0u;

    if (tid < 128) {
        biass[tid] = Bb[(size_t)d * 4096 + col0 + tid]
                   + Bb[(size_t)d * 4096 + 2048 + col0 + tid];
    }

    const int wm  = (wid & 3) * 32;
    const int wn  = (wid >> 2) * 64;
    const int grp = lane >> 2;
    const int thr = lane & 3;

    const int aM  = lane & 15;
    const int aK8 = (lane >> 4) << 3;

    const int lrow = tid >> 3;
    const int lkp  = (tid & 7) * 4;

    float cr[2][8][4];
#pragma unroll
    for (int mt = 0; mt < 2; mt++)
#pragma unroll
        for (int nt = 0; nt < 8; nt++)
#pragma unroll
            for (int q = 0; q < 4; q++) cr[mt][nt][q] = 0.f;

    float4 ra[4], rb[4];
#pragma unroll
    for (int i = 0; i < 4; i++) {
        int r = lrow + i * 32;
        ra[i] = *(const float4*)(Am + (size_t)r * ID + lkp);
        rb[i] = *(const float4*)(Bm + (size_t)r * ID + lkp);
    }

#pragma unroll 1
    for (int c = 0; c < 16; c++) {
        __syncthreads();
#pragma unroll
        for (int i = 0; i < 4; i++) {
            int r = lrow + i * 32;
            __half2 a01 = __floats2half2_rn(ra[i].x, ra[i].y);
            __half2 a23 = __floats2half2_rn(ra[i].z, ra[i].w);
            __half2 b01 = __floats2half2_rn(rb[i].x, rb[i].y);
            __half2 b23 = __floats2half2_rn(rb[i].z, rb[i].w);
            uint2 va = make_uint2(*(uint32_t*)&a01, *(uint32_t*)&a23);
            uint2 vb = make_uint2(*(uint32_t*)&b01, *(uint32_t*)&b23);
            *(uint2*)&As[r][lkp] = va;
            *(uint2*)&Bs[r][lkp] = vb;
        }
        __syncthreads();

        if (c < 15) {
            const int kk = (c + 1) * 32;
#pragma unroll
            for (int i = 0; i < 4; i++) {
                int r = lrow + i * 32;
                ra[i] = *(const float4*)(Am + (size_t)r * ID + kk + lkp);
                rb[i] = *(const float4*)(Bm + (size_t)r * ID + kk + lkp);
            }
        }

#pragma unroll
        for (int ks = 0; ks < 2; ks++) {
            const int k0 = ks * 16;
            uint32_t af[2][4];
#pragma unroll
            for (int mt = 0; mt < 2; mt++) {
                uint32_t addr = smem_u32(&As[wm + mt * 16 + aM][k0 + aK8]);
                asm volatile(
                    "ldmatrix.sync.aligned.m8n8.x4.shared.b16 {%0,%1,%2,%3}, [%4];"
                    : "=r"(af[mt][0]), "=r"(af[mt][1]), "=r"(af[mt][2]), "=r"(af[mt][3])
                    : "r"(addr));
            }
#pragma unroll
            for (int nt16 = 0; nt16 < 4; nt16++) {
                uint32_t r0, r1, r2, r3;
                uint32_t addr = smem_u32(&Bs[wn + nt16 * 16 + aM][k0 + aK8]);
                asm volatile(
                    "ldmatrix.sync.aligned.m8n8.x4.shared.b16 {%0,%1,%2,%3}, [%4];"
                    : "=r"(r0), "=r"(r1), "=r"(r2), "=r"(r3) : "r"(addr));
#pragma unroll
                for (int mt = 0; mt < 2; mt++) {
                    asm volatile(
                        "mma.sync.aligned.m16n8k16.row.col.f32.f16.f16.f32 "
                        "{%0,%1,%2,%3}, {%4,%5,%6,%7}, {%8,%9}, {%0,%1,%2,%3};"
                        : "+f"(cr[mt][2 * nt16][0]), "+f"(cr[mt][2 * nt16][1]),
                          "+f"(cr[mt][2 * nt16][2]), "+f"(cr[mt][2 * nt16][3])
                        : "r"(af[mt][0]), "r"(af[mt][1]), "r"(af[mt][2]), "r"(af[mt][3]),
                          "r"(r0), "r"(r2));
                    asm volatile(
                        "mma.sync.aligned.m16n8k16.row.col.f32.f16.f16.f32 "
                        "{%0,%1,%2,%3}, {%4,%5,%6,%7}, {%8,%9}, {%0,%1,%2,%3};"
                        : "+f"(cr[mt][2 * nt16 + 1][0]), "+f"(cr[mt][2 * nt16 + 1][1]),
                          "+f"(cr[mt][2 * nt16 + 1][2]), "+f"(cr[mt][2 * nt16 + 1][3])
                        : "r"(af[mt][0]), "r"(af[mt][1]), "r"(af[mt][2]), "r"(af[mt][3]),
                          "r"(r1), "r"(r3));
                }
            }
        }
    }

#pragma unroll
    for (int mt = 0; mt < 2; mt++) {
        const int m0 = row0 + wm + mt * 16 + grp;
#pragma unroll
        for (int nt = 0; nt < 8; nt++) {
            const int cl = wn + nt * 8 + 2 * thr;
            float2 v0 = make_float2(cr[mt][nt][0] + biass[cl],
                                    cr[mt][nt][1] + biass[cl + 1]);
            float2 v1 = make_float2(cr[mt][nt][2] + biass[cl],
                                    cr[mt][nt][3] + biass[cl + 1]);
            *(float2*)(C + (size_t)m0 * NG + col0 + cl)       = v0;
            *(float2*)(C + (size_t)(m0 + 8) * NG + col0 + cl) = v1;
        }
    }
}

// ===========================================================================
// Phase 2: persistent bidirectional recurrence, fp16 mma.m16n8k16.
// Sync via per-producer flags (no global atomic barrier). Per-thread cp.async
// staging (R7 scheme) over padded g_h.
// ===========================================================================
__device__ __forceinline__ float sigmoidf_(float x) {
    return 1.f / (1.f + __expf(-x));
}

#define HS_BYTES  (512 * HS_STRIDE * 2)

__global__ __launch_bounds__(512, 1) void lstm_rec(const float* __restrict__ R,
                                                   const int*   __restrict__ seq,
                                                   const float* __restrict__ h0,
                                                   const float* __restrict__ c0,
                                                   const float* __restrict__ P,
                                                   float* __restrict__ out) {
    extern __shared__ __half hs[];           // [512][HS_STRIDE] fp16 h
    __shared__ float accs[4][4][8][65];      // [kg][gate][hl][b]
    __shared__ float xgs[4][64][9];          // [gate][b][hl]
    __shared__ float cs[8][64], c0s[8][64], h0s[8][64];
    __shared__ float Ps[3][8];
    __shared__ int   slen[BSZ];

    const int blk = blockIdx.x;
    const int d   = blk >> 6;
    const int myj = blk & 63;                // producer index within direction
    const int hb  = myj * 8;
    const int tid = threadIdx.x;
    const int wid = tid >> 5, lane = tid & 31;
    const int grp = lane >> 2, thr = lane & 3;
    const int mg  = wid & 1;                 // batch half
    const int ng  = (wid >> 1) & 1;          // gate pair {2ng, 2ng+1}
    const int kg  = wid >> 2;                // k quarter (0..3)
    const int m0  = mg * 32;
    const int kb0 = kg * 128;

    const uint32_t hs_b = smem_u32(hs);

    // ldmatrix x4.trans lane components
    const int seg   = lane >> 3;
    const int laneK = ((seg >> 1) << 3) + (lane & 7);
    const int laneM = (seg & 1) << 3;

    // ---- publish initial h as early as possible ----
    if (tid < BSZ) slen[tid] = seq[tid];
    {
        int hl = tid >> 6, b = tid & 63;
        size_t idx = ((size_t)d * BSZ + b) * HID + hb + hl;
        float hv = h0[idx], cv = c0[idx];
        h0s[hl][b] = hv; c0s[hl][b] = cv; cs[hl][b] = cv;
        g_h[0][d][hb + hl][b] = __float2half(hv);
    }
    __syncthreads();
    if (tid == 0) {
        __threadfence();
        asm volatile("st.global.u32 [%0], %1;"
                     :: "l"(&g_flag[d][myj]), "r"(1u) : "memory");
    }

    // Preload R fragments (fp16) — constant across steps (overlaps flag fanout).
    uint32_t Rlo[2][8], Rhi[2][8];
#pragma unroll
    for (int nt2 = 0; nt2 < 2; nt2++) {
        const float* Rrow = R + ((size_t)d * NG + (2 * ng + nt2) * 512 + hb + grp) * HID + kb0;
#pragma unroll
        for (int ks = 0; ks < 8; ks++) {
            const int k = ks * 16;
            __half2 lo = __floats2half2_rn(Rrow[k + 2 * thr], Rrow[k + 2 * thr + 1]);
            __half2 hi = __floats2half2_rn(Rrow[k + 2 * thr + 8], Rrow[k + 2 * thr + 9]);
            Rlo[nt2][ks] = *(uint32_t*)&lo;
            Rhi[nt2][ks] = *(uint32_t*)&hi;
        }
    }
    if (tid < 24) {
        int w = tid / 8, hl = tid % 8;
        Ps[w][hl] = P[(size_t)d * 1536 + w * 512 + hb + hl];
    }

    float* Yh = out + 33554432;
    float* Yc = Yh + 65536;

    const int xb = tid >> 3, xq = tid & 7;
    const int xgate = xq >> 1, xh4 = (xq & 1) * 4;

    const int sgrp   = tid >> 7;              // staging group == warp's kg
    const int slocal = tid & 127;
    // each thread polls one producer flag of its own k-quarter
    unsigned* mflag = &g_flag[d][sgrp * 16 + (slocal & 15)];

    for (int s = 0; s < SLEN; ++s) {
        const int t   = d ? (SLEN - 1 - s) : s;
        const int cur = s & 1, nxt = cur ^ 1;
        const unsigned need = (unsigned)(s + 1);

        // Prefetch this block's Xg tile (global load, long latency)
        const float* xp = g_Xg + (((size_t)d * SLEN + t) * BSZ + xb) * NG
                        + xgate * 512 + hb + xh4;
        float4 xv = *(const float4*)xp;

        // Stage Xg into smem (WAR-safe: previous step ended with __syncthreads)
        xgs[xgate][xb][xh4 + 0] = xv.x;
        xgs[xgate][xb][xh4 + 1] = xv.y;
        xgs[xgate][xb][xh4 + 2] = xv.z;
        xgs[xgate][xb][xh4 + 3] = xv.w;

        // Wait for this quarter's 16 producers (distinct-address acquire polls)
        {
            unsigned v;
            do {
                asm volatile("ld.acquire.gpu.u32 %0, [%1];"
                             : "=r"(v) : "l"(mflag) : "memory");
            } while (v < need);
        }
        asm volatile("bar.sync %0, 128;" :: "r"(1 + sgrp) : "memory");

        // Stage own k-quarter: 18KB contiguous (padded layout), 9x16B per thread
        {
            const char* src = (const char*)&g_h[cur][d][sgrp * 128][0];
            uint32_t    dst = hs_b + (uint32_t)sgrp * CHUNK_BYTES;
#pragma unroll
            for (int i = 0; i < 9; i++) {
                uint32_t off = (uint32_t)(slocal + i * 128) * 16;
                asm volatile("cp.async.cg.shared.global [%0], [%1], 16;"
                             :: "r"(dst + off), "l"(src + off));
            }
        }
        asm volatile("cp.async.commit_group;");
        asm volatile("cp.async.wait_group 0;");
        asm volatile("bar.sync %0, 128;" :: "r"(1 + sgrp) : "memory");

        // MMA: partial G over this warp's k quarter (8 k16 steps).
        float acc[2][2][4];
#pragma unroll
        for (int mtf = 0; mtf < 2; mtf++)
#pragma unroll
            for (int nt2 = 0; nt2 < 2; nt2++)
#pragma unroll
                for (int q = 0; q < 4; q++) acc[mtf][nt2][q] = 0.f;

#pragma unroll
        for (int ks = 0; ks < 8; ks++) {
            const int kb = kb0 + ks * 16 + laneK;
#pragma unroll
            for (int mtf = 0; mtf < 2; mtf++) {
                const int mb = m0 + mtf * 16 + laneM;
                uint32_t addr = hs_b + (uint32_t)(kb * HS_STRIDE + mb) * 2;
                uint32_t a0, a1, a2, a3;
                asm volatile(
                    "ldmatrix.sync.aligned.m8n8.x4.trans.shared.b16 {%0,%1,%2,%3}, [%4];"
                    : "=r"(a0), "=r"(a1), "=r"(a2), "=r"(a3) : "r"(addr));
#pragma unroll
                for (int nt2 = 0; nt2 < 2; nt2++) {
                    asm volatile(
                        "mma.sync.aligned.m16n8k16.row.col.f32.f16.f16.f32 "
                        "{%0,%1,%2,%3}, {%4,%5,%6,%7}, {%8,%9}, {%0,%1,%2,%3};"
                        : "+f"(acc[mtf][nt2][0]), "+f"(acc[mtf][nt2][1]),
                          "+f"(acc[mtf][nt2][2]), "+f"(acc[mtf][nt2][3])
                        : "r"(a0), "r"(a1), "r"(a2), "r"(a3),
                          "r"(Rlo[nt2][ks]), "r"(Rhi[nt2][ks]));
                }
            }
        }

        // Exchange: fragments -> accs[kg][gate][hl][b]
#pragma unroll
        for (int mtf = 0; mtf < 2; mtf++) {
            const int m = m0 + mtf * 16 + grp;
#pragma unroll
            for (int nt2 = 0; nt2 < 2; nt2++) {
                const int g = 2 * ng + nt2;
                accs[kg][g][2 * thr]    [m]     = acc[mtf][nt2][0];
                accs[kg][g][2 * thr + 1][m]     = acc[mtf][nt2][1];
                accs[kg][g][2 * thr]    [m + 8] = acc[mtf][nt2][2];
                accs[kg][g][2 * thr + 1][m + 8] = acc[mtf][nt2][3];
            }
        }
        __syncthreads();

        // Elementwise LSTM cell + peephole + mask (512 threads, 1 elem each)
        {
            int hl = tid >> 6, b = tid & 63;
            float gi = accs[0][0][hl][b] + accs[1][0][hl][b]
                     + accs[2][0][hl][b] + accs[3][0][hl][b] + xgs[0][b][hl];
            float go = accs[0][1][hl][b] + accs[1][1][hl][b]
                     + accs[2][1][hl][b] + accs[3][1][hl][b] + xgs[1][b][hl];
            float gf = accs[0][2][hl][b] + accs[1][2][hl][b]
                     + accs[2][2][hl][b] + accs[3][2][hl][b] + xgs[2][b][hl];
            float gg = accs[0][3][hl][b] + accs[1][3][hl][b]
                     + accs[2][3][hl][b] + accs[3][3][hl][b] + xgs[3][b][hl];
            float c  = cs[hl][b];
            float iv = sigmoidf_(gi + Ps[0][hl] * c);
            float fv = sigmoidf_(gf + Ps[1][hl] * c);
            float ct = tanhf(gg);
            float cn = fv * c + iv * ct;
            float ov = sigmoidf_(go + Ps[2][hl] * cn);
            float hn = ov * tanhf(cn);
            if (t >= slen[b]) { hn = h0s[hl][b]; cn = c0s[hl][b]; }
            cs[hl][b] = cn;
            g_h[nxt][d][hb + hl][b] = __float2half(hn);
            out[(((size_t)t * 2 + d) * BSZ + b) * HID + hb + hl] = hn;
            if (s == SLEN - 1) {
                size_t fi = ((size_t)d * BSZ + b) * HID + hb + hl;
                Yh[fi] = hn;
                Yc[fi] = cn;
            }
        }
        __syncthreads();                      // all h(s+1) rows written
        if (tid == 0) {
            __threadfence();
            asm volatile("st.global.u32 [%0], %1;"
                         :: "l"(&g_flag[d][myj]), "r"((unsigned)(s + 2)) : "memory");
        }
    }
}

// ---------------------------------------------------------------------------
extern "C" void kernel_launch(void* const* d_in, const int* in_sizes, int n_in,
                              void* d_out, int out_size) {
    const float* X   = (const float*)d_in[0];
    const float* W   = (const float*)d_in[1];
    const float* R   = (const float*)d_in[2];
    const float* Bb  = (const float*)d_in[3];
    const int*   sl  = (const int*)  d_in[4];
    const float* h0  = (const float*)d_in[5];
    const float* c0  = (const float*)d_in[6];
    const float* P   = (const float*)d_in[7];
    float* out = (float*)d_out;

    static int configured = 0;
    if (!configured) {
        cudaFuncSetAttribute(lstm_rec, cudaFuncAttributeMaxDynamicSharedMemorySize,
                             HS_BYTES);
        configured = 1;
    }

    gemm_xw_fp16<<<dim3(16, 256, 2), 256>>>(X, W, Bb);
    lstm_rec<<<NBLK, 512, HS_BYTES>>>(R, sl, h0, c0, P, out);
}

// round 10
// speedup vs baseline: 2.7153x; 2.7153x over previous
#include <cuda_runtime.h>
#include <cuda_fp16.h>
#include <cstdint>

// Problem constants
#define SLEN 512
#define BSZ  64
#define ID   512
#define HID  512
#define NG   2048   // 4*H
#define NBLK 128    // total persistent blocks for phase 2
#define NBLKD 64    // per direction

#define HS_STRIDE 72                       // padded batch stride (halves)
#define CHUNK_BYTES (128 * HS_STRIDE * 2)  // one k-quarter = 18432 B

// Scratch (device globals: allocation-free)
static __device__ float    g_Xg[134217728];             // (D, S, B, 4H)
static __device__ __half   g_h[2][2][HID][HS_STRIDE];   // padded: src == smem layout
static __device__ unsigned g_barD[2];

__device__ __forceinline__ uint32_t smem_u32(const void* p) {
    uint32_t a;
    asm("{ .reg .u64 t; cvta.to.shared.u64 t, %1; cvt.u32.u64 %0, t; }"
        : "=r"(a) : "l"(p));
    return a;
}

// ===========================================================================
// Phase 1: Xg[d, r, :] = X[r,:] @ W[d]^T + Wb[d] + Rb[d]
// fp16 mma.sync.m16n8k16, fp32 accum (unchanged — proven).
// ===========================================================================
#define PSTR 40

__global__ __launch_bounds__(256) void gemm_xw_fp16(const float* __restrict__ X,
                                                    const float* __restrict__ W,
                                                    const float* __restrict__ Bb) {
    __shared__ __half As[128][PSTR];
    __shared__ __half Bs[128][PSTR];
    __shared__ float biass[128];

    const int tid  = threadIdx.x;
    const int wid  = tid >> 5, lane = tid & 31;
    const int d    = blockIdx.z;
    const int col0 = blockIdx.x * 128;
    const int row0 = blockIdx.y * 128;
    const float* Am = X + (size_t)row0 * ID;
    const float* Bm = W + ((size_t)d * NG + col0) * ID;
    float* C = g_Xg + (size_t)d * SLEN * BSZ * NG;

    if (blockIdx.x == 0 && blockIdx.y == 0 && blockIdx.z == 0 && tid == 0) {
        g_barD[0] = 0u;
        g_barD[1] = 0u;
    }

    if (tid < 128) {
        biass[tid] = Bb[(size_t)d * 4096 + col0 + tid]
                   + Bb[(size_t)d * 4096 + 2048 + col0 + tid];
    }

    const int wm  = (wid & 3) * 32;
    const int wn  = (wid >> 2) * 64;
    const int grp = lane >> 2;
    const int thr = lane & 3;

    const int aM  = lane & 15;
    const int aK8 = (lane >> 4) << 3;

    const int lrow = tid >> 3;
    const int lkp  = (tid & 7) * 4;

    float cr[2][8][4];
#pragma unroll
    for (int mt = 0; mt < 2; mt++)
#pragma unroll
        for (int nt = 0; nt < 8; nt++)
#pragma unroll
            for (int q = 0; q < 4; q++) cr[mt][nt][q] = 0.f;

    float4 ra[4], rb[4];
#pragma unroll
    for (int i = 0; i < 4; i++) {
        int r = lrow + i * 32;
        ra[i] = *(const float4*)(Am + (size_t)r * ID + lkp);
        rb[i] = *(const float4*)(Bm + (size_t)r * ID + lkp);
    }

#pragma unroll 1
    for (int c = 0; c < 16; c++) {
        __syncthreads();
#pragma unroll
        for (int i = 0; i < 4; i++) {
            int r = lrow + i * 32;
            __half2 a01 = __floats2half2_rn(ra[i].x, ra[i].y);
            __half2 a23 = __floats2half2_rn(ra[i].z, ra[i].w);
            __half2 b01 = __floats2half2_rn(rb[i].x, rb[i].y);
            __half2 b23 = __floats2half2_rn(rb[i].z, rb[i].w);
            uint2 va = make_uint2(*(uint32_t*)&a01, *(uint32_t*)&a23);
            uint2 vb = make_uint2(*(uint32_t*)&b01, *(uint32_t*)&b23);
            *(uint2*)&As[r][lkp] = va;
            *(uint2*)&Bs[r][lkp] = vb;
        }
        __syncthreads();

        if (c < 15) {
            const int kk = (c + 1) * 32;
#pragma unroll
            for (int i = 0; i < 4; i++) {
                int r = lrow + i * 32;
                ra[i] = *(const float4*)(Am + (size_t)r * ID + kk + lkp);
                rb[i] = *(const float4*)(Bm + (size_t)r * ID + kk + lkp);
            }
        }

#pragma unroll
        for (int ks = 0; ks < 2; ks++) {
            const int k0 = ks * 16;
            uint32_t af[2][4];
#pragma unroll
            for (int mt = 0; mt < 2; mt++) {
                uint32_t addr = smem_u32(&As[wm + mt * 16 + aM][k0 + aK8]);
                asm volatile(
                    "ldmatrix.sync.aligned.m8n8.x4.shared.b16 {%0,%1,%2,%3}, [%4];"
                    : "=r"(af[mt][0]), "=r"(af[mt][1]), "=r"(af[mt][2]), "=r"(af[mt][3])
                    : "r"(addr));
            }
#pragma unroll
            for (int nt16 = 0; nt16 < 4; nt16++) {
                uint32_t r0, r1, r2, r3;
                uint32_t addr = smem_u32(&Bs[wn + nt16 * 16 + aM][k0 + aK8]);
                asm volatile(
                    "ldmatrix.sync.aligned.m8n8.x4.shared.b16 {%0,%1,%2,%3}, [%4];"
                    : "=r"(r0), "=r"(r1), "=r"(r2), "=r"(r3) : "r"(addr));
#pragma unroll
                for (int mt = 0; mt < 2; mt++) {
                    asm volatile(
                        "mma.sync.aligned.m16n8k16.row.col.f32.f16.f16.f32 "
                        "{%0,%1,%2,%3}, {%4,%5,%6,%7}, {%8,%9}, {%0,%1,%2,%3};"
                        : "+f"(cr[mt][2 * nt16][0]), "+f"(cr[mt][2 * nt16][1]),
                          "+f"(cr[mt][2 * nt16][2]), "+f"(cr[mt][2 * nt16][3])
                        : "r"(af[mt][0]), "r"(af[mt][1]), "r"(af[mt][2]), "r"(af[mt][3]),
                          "r"(r0), "r"(r2));
                    asm volatile(
                        "mma.sync.aligned.m16n8k16.row.col.f32.f16.f16.f32 "
                        "{%0,%1,%2,%3}, {%4,%5,%6,%7}, {%8,%9}, {%0,%1,%2,%3};"
                        : "+f"(cr[mt][2 * nt16 + 1][0]), "+f"(cr[mt][2 * nt16 + 1][1]),
                          "+f"(cr[mt][2 * nt16 + 1][2]), "+f"(cr[mt][2 * nt16 + 1][3])
                        : "r"(af[mt][0]), "r"(af[mt][1]), "r"(af[mt][2]), "r"(af[mt][3]),
                          "r"(r1), "r"(r3));
                }
            }
        }
    }

#pragma unroll
    for (int mt = 0; mt < 2; mt++) {
        const int m0 = row0 + wm + mt * 16 + grp;
#pragma unroll
        for (int nt = 0; nt < 8; nt++) {
            const int cl = wn + nt * 8 + 2 * thr;
            float2 v0 = make_float2(cr[mt][nt][0] + biass[cl],
                                    cr[mt][nt][1] + biass[cl + 1]);
            float2 v1 = make_float2(cr[mt][nt][2] + biass[cl],
                                    cr[mt][nt][3] + biass[cl + 1]);
            *(float2*)(C + (size_t)m0 * NG + col0 + cl)       = v0;
            *(float2*)(C + (size_t)(m0 + 8) * NG + col0 + cl) = v1;
        }
    }
}

// ===========================================================================
// Phase 2: persistent bidirectional recurrence, fp16 mma.m16n8k16.
// Per-direction atomic grid barrier (proven R7 scheme). Padded g_h staging
// via per-thread cp.async in 2 commit groups (overlap transfer with MMA).
// ===========================================================================
__device__ __forceinline__ void grid_barrier(unsigned* ctr, unsigned target) {
    __syncthreads();
    if (threadIdx.x == 0) {
        __threadfence();
        atomicAdd(ctr, 1u);
        unsigned v;
        do {
            asm volatile("ld.acquire.gpu.u32 %0, [%1];" : "=r"(v) : "l"(ctr) : "memory");
        } while (v < target);
    }
    __syncthreads();
}

__device__ __forceinline__ float sigmoidf_(float x) {
    return 1.f / (1.f + __expf(-x));
}
// Overflow-safe fast tanh: e = exp(-2|x|) in (0,1]; result = sign(x)*(1-e)/(1+e)
__device__ __forceinline__ float tanhf_(float x) {
    float ax = fabsf(x);
    float e  = __expf(-2.f * ax);
    float r  = (1.f - e) / (1.f + e);
    return copysignf(r, x);
}

#define HS_BYTES  (512 * HS_STRIDE * 2)

__global__ __launch_bounds__(512, 1) void lstm_rec(const float* __restrict__ R,
                                                   const int*   __restrict__ seq,
                                                   const float* __restrict__ h0,
                                                   const float* __restrict__ c0,
                                                   const float* __restrict__ P,
                                                   float* __restrict__ out) {
    extern __shared__ __half hs[];           // [512][HS_STRIDE] fp16 h
    __shared__ float accs[4][4][8][65];      // [kg][gate][hl][b]
    __shared__ float xgs[4][64][9];          // [gate][b][hl]
    __shared__ float cs[8][64], c0s[8][64], h0s[8][64];
    __shared__ float Ps[3][8];
    __shared__ int   slen[BSZ];

    const int blk = blockIdx.x;
    const int d   = blk >> 6;
    const int hb  = (blk & 63) * 8;
    const int tid = threadIdx.x;
    const int wid = tid >> 5, lane = tid & 31;
    const int grp = lane >> 2, thr = lane & 3;
    const int mg  = wid & 1;                 // batch half
    const int ng  = (wid >> 1) & 1;          // gate pair {2ng, 2ng+1}
    const int kg  = wid >> 2;                // k quarter (0..3)
    const int m0  = mg * 32;
    const int kb0 = kg * 128;

    unsigned* bar = &g_barD[d];

    const uint32_t hs_b = smem_u32(hs);

    // ldmatrix x4.trans lane components
    const int seg   = lane >> 3;
    const int laneK = ((seg >> 1) << 3) + (lane & 7);
    const int laneM = (seg & 1) << 3;

    // Preload R fragments (fp16) — constant across steps.
    uint32_t Rlo[2][8], Rhi[2][8];
#pragma unroll
    for (int nt2 = 0; nt2 < 2; nt2++) {
        const float* Rrow = R + ((size_t)d * NG + (2 * ng + nt2) * 512 + hb + grp) * HID + kb0;
#pragma unroll
        for (int ks = 0; ks < 8; ks++) {
            const int k = ks * 16;
            __half2 lo = __floats2half2_rn(Rrow[k + 2 * thr], Rrow[k + 2 * thr + 1]);
            __half2 hi = __floats2half2_rn(Rrow[k + 2 * thr + 8], Rrow[k + 2 * thr + 9]);
            Rlo[nt2][ks] = *(uint32_t*)&lo;
            Rhi[nt2][ks] = *(uint32_t*)&hi;
        }
    }

    if (tid < BSZ) slen[tid] = seq[tid];
    if (tid < 24) {
        int w = tid / 8, hl = tid % 8;
        Ps[w][hl] = P[(size_t)d * 1536 + w * 512 + hb + hl];
    }
    {
        int hl = tid >> 6, b = tid & 63;
        size_t idx = ((size_t)d * BSZ + b) * HID + hb + hl;
        float hv = h0[idx], cv = c0[idx];
        h0s[hl][b] = hv; c0s[hl][b] = cv; cs[hl][b] = cv;
        g_h[0][d][hb + hl][b] = __float2half(hv);
    }

    unsigned target = NBLKD;
    grid_barrier(bar, target); target += NBLKD;   // h0 visible (per dir)

    float* Yh = out + 33554432;
    float* Yc = Yh + 65536;

    const int xb = tid >> 3, xq = tid & 7;
    const int xgate = xq >> 1, xh4 = (xq & 1) * 4;

    const int sgrp   = tid >> 7;              // staging group == warp's kg
    const int slocal = tid & 127;

    for (int s = 0; s < SLEN; ++s) {
        const int t   = d ? (SLEN - 1 - s) : s;
        const int cur = s & 1, nxt = cur ^ 1;

        // Prefetch this block's Xg tile before the barrier
        const float* xp = g_Xg + (((size_t)d * SLEN + t) * BSZ + xb) * NG
                        + xgate * 512 + hb + xh4;
        float4 xv = *(const float4*)xp;

        grid_barrier(bar, target); target += NBLKD;   // h(t) ready (this dir)

        xgs[xgate][xb][xh4 + 0] = xv.x;
        xgs[xgate][xb][xh4 + 1] = xv.y;
        xgs[xgate][xb][xh4 + 2] = xv.z;
        xgs[xgate][xb][xh4 + 3] = xv.w;

        // Stage own k-quarter in 2 commit groups:
        //   A: i 0..4 (rows 0..71 of quarter)  B: i 5..8 (rows 72..127)
        {
            const char* src = (const char*)&g_h[cur][d][sgrp * 128][0];
            uint32_t    dst = hs_b + (uint32_t)sgrp * CHUNK_BYTES;
#pragma unroll
            for (int i = 0; i < 5; i++) {
                uint32_t off = (uint32_t)(slocal + i * 128) * 16;
                asm volatile("cp.async.cg.shared.global [%0], [%1], 16;"
                             :: "r"(dst + off), "l"(src + off));
            }
            asm volatile("cp.async.commit_group;");
#pragma unroll
            for (int i = 5; i < 9; i++) {
                uint32_t off = (uint32_t)(slocal + i * 128) * 16;
                asm volatile("cp.async.cg.shared.global [%0], [%1], 16;"
                             :: "r"(dst + off), "l"(src + off));
            }
            asm volatile("cp.async.commit_group;");
        }

        float acc[2][2][4];
#pragma unroll
        for (int mtf = 0; mtf < 2; mtf++)
#pragma unroll
            for (int nt2 = 0; nt2 < 2; nt2++)
#pragma unroll
                for (int q = 0; q < 4; q++) acc[mtf][nt2][q] = 0.f;

        // Wait group A (rows 0..71 ⊇ ks 0..3), MMA first half while B lands.
        asm volatile("cp.async.wait_group 1;");
        asm volatile("bar.sync %0, 128;" :: "r"(1 + sgrp) : "memory");

#pragma unroll
        for (int ks = 0; ks < 4; ks++) {
            const int kb = kb0 + ks * 16 + laneK;
#pragma unroll
            for (int mtf = 0; mtf < 2; mtf++) {
                const int mb = m0 + mtf * 16 + laneM;
                uint32_t addr = hs_b + (uint32_t)(kb * HS_STRIDE + mb) * 2;
                uint32_t a0, a1, a2, a3;
                asm volatile(
                    "ldmatrix.sync.aligned.m8n8.x4.trans.shared.b16 {%0,%1,%2,%3}, [%4];"
                    : "=r"(a0), "=r"(a1), "=r"(a2), "=r"(a3) : "r"(addr));
#pragma unroll
                for (int nt2 = 0; nt2 < 2; nt2++) {
                    asm volatile(
                        "mma.sync.aligned.m16n8k16.row.col.f32.f16.f16.f32 "
                        "{%0,%1,%2,%3}, {%4,%5,%6,%7}, {%8,%9}, {%0,%1,%2,%3};"
                        : "+f"(acc[mtf][nt2][0]), "+f"(acc[mtf][nt2][1]),
                          "+f"(acc[mtf][nt2][2]), "+f"(acc[mtf][nt2][3])
                        : "r"(a0), "r"(a1), "r"(a2), "r"(a3),
                          "r"(Rlo[nt2][ks]), "r"(Rhi[nt2][ks]));
                }
            }
        }

        asm volatile("cp.async.wait_group 0;");
        asm volatile("bar.sync %0, 128;" :: "r"(1 + sgrp) : "memory");

#pragma unroll
        for (int ks = 4; ks < 8; ks++) {
            const int kb = kb0 + ks * 16 + laneK;
#pragma unroll
            for (int mtf = 0; mtf < 2; mtf++) {
                const int mb = m0 + mtf * 16 + laneM;
                uint32_t addr = hs_b + (uint32_t)(kb * HS_STRIDE + mb) * 2;
                uint32_t a0, a1, a2, a3;
                asm volatile(
                    "ldmatrix.sync.aligned.m8n8.x4.trans.shared.b16 {%0,%1,%2,%3}, [%4];"
                    : "=r"(a0), "=r"(a1), "=r"(a2), "=r"(a3) : "r"(addr));
#pragma unroll
                for (int nt2 = 0; nt2 < 2; nt2++) {
                    asm volatile(
                        "mma.sync.aligned.m16n8k16.row.col.f32.f16.f16.f32 "
                        "{%0,%1,%2,%3}, {%4,%5,%6,%7}, {%8,%9}, {%0,%1,%2,%3};"
                        : "+f"(acc[mtf][nt2][0]), "+f"(acc[mtf][nt2][1]),
                          "+f"(acc[mtf][nt2][2]), "+f"(acc[mtf][nt2][3])
                        : "r"(a0), "r"(a1), "r"(a2), "r"(a3),
                          "r"(Rlo[nt2][ks]), "r"(Rhi[nt2][ks]));
                }
            }
        }

        // Exchange: fragments -> accs[kg][gate][hl][b]
#pragma unroll
        for (int mtf = 0; mtf < 2; mtf++) {
            const int m = m0 + mtf * 16 + grp;
#pragma unroll
            for (int nt2 = 0; nt2 < 2; nt2++) {
                const int g = 2 * ng + nt2;
                accs[kg][g][2 * thr]    [m]     = acc[mtf][nt2][0];
                accs[kg][g][2 * thr + 1][m]     = acc[mtf][nt2][1];
                accs[kg][g][2 * thr]    [m + 8] = acc[mtf][nt2][2];
                accs[kg][g][2 * thr + 1][m + 8] = acc[mtf][nt2][3];
            }
        }
        __syncthreads();

        // Elementwise LSTM cell + peephole + mask (512 threads, 1 elem each)
        {
            int hl = tid >> 6, b = tid & 63;
            float gi = accs[0][0][hl][b] + accs[1][0][hl][b]
                     + accs[2][0][hl][b] + accs[3][0][hl][b] + xgs[0][b][hl];
            float go = accs[0][1][hl][b] + accs[1][1][hl][b]
                     + accs[2][1][hl][b] + accs[3][1][hl][b] + xgs[1][b][hl];
            float gf = accs[0][2][hl][b] + accs[1][2][hl][b]
                     + accs[2][2][hl][b] + accs[3][2][hl][b] + xgs[2][b][hl];
            float gg = accs[0][3][hl][b] + accs[1][3][hl][b]
                     + accs[2][3][hl][b] + accs[3][3][hl][b] + xgs[3][b][hl];
            float c  = cs[hl][b];
            float iv = sigmoidf_(gi + Ps[0][hl] * c);
            float fv = sigmoidf_(gf + Ps[1][hl] * c);
            float ct = tanhf_(gg);
            float cn = fv * c + iv * ct;
            float ov = sigmoidf_(go + Ps[2][hl] * cn);
            float hn = ov * tanhf_(cn);
            if (t >= slen[b]) { hn = h0s[hl][b]; cn = c0s[hl][b]; }
            cs[hl][b] = cn;
            g_h[nxt][d][hb + hl][b] = __float2half(hn);
            out[(((size_t)t * 2 + d) * BSZ + b) * HID + hb + hl] = hn;
            if (s == SLEN - 1) {
                size_t fi = ((size_t)d * BSZ + b) * HID + hb + hl;
                Yh[fi] = hn;
                Yc[fi] = cn;
            }
        }
    }
}

// ---------------------------------------------------------------------------
extern "C" void kernel_launch(void* const* d_in, const int* in_sizes, int n_in,
                              void* d_out, int out_size) {
    const float* X   = (const float*)d_in[0];
    const float* W   = (const float*)d_in[1];
    const float* R   = (const float*)d_in[2];
    const float* Bb  = (const float*)d_in[3];
    const int*   sl  = (const int*)  d_in[4];
    const float* h0  = (const float*)d_in[5];
    const float* c0  = (const float*)d_in[6];
    const float* P   = (const float*)d_in[7];
    float* out = (float*)d_out;

    static int configured = 0;
    if (!configured) {
        cudaFuncSetAttribute(lstm_rec, cudaFuncAttributeMaxDynamicSharedMemorySize,
                             HS_BYTES);
        configured = 1;
    }

    gemm_xw_fp16<<<dim3(16, 256, 2), 256>>>(X, W, Bb);
    lstm_rec<<<NBLK, 512, HS_BYTES>>>(R, sl, h0, c0, P, out);
}

// round 11
// speedup vs baseline: 2.7933x; 1.0287x over previous
#include <cuda_runtime.h>
#include <cuda_fp16.h>
#include <cstdint>

// Problem constants
#define SLEN 512
#define BSZ  64
#define ID   512
#define HID  512
#define NG   2048   // 4*H
#define NBLK 128    // total persistent blocks for phase 2
#define NBLKD 64    // per direction

#define HS_STRIDE 72                       // padded batch stride (halves)
#define CHUNK_BYTES (128 * HS_STRIDE * 2)  // one k-quarter = 18432 B

// Scratch (device globals: allocation-free)
static __device__ float    g_Xg[134217728];             // (D, S, B, 4H)
static __device__ __half   g_Xh[16777216];              // X in fp16
static __device__ __half   g_Wh[2097152];               // W in fp16
static __device__ __half   g_h[2][2][HID][HS_STRIDE];   // padded h state
static __device__ unsigned g_barD[2];

__device__ __forceinline__ uint32_t smem_u32(const void* p) {
    uint32_t a;
    asm("{ .reg .u64 t; cvta.to.shared.u64 t, %1; cvt.u32.u64 %0, t; }"
        : "=r"(a) : "l"(p));
    return a;
}

// ===========================================================================
// Phase 0: convert X and W to fp16 scratch (linear copy)
// ===========================================================================
#define NX4 4194304u   // X float4 count (16777216 / 4)
#define NT4 4718592u   // total float4 count ((16777216+2097152)/4)

__global__ __launch_bounds__(256) void convert_fp16(const float* __restrict__ X,
                                                    const float* __restrict__ W) {
    uint32_t i = blockIdx.x * 256u + threadIdx.x;
    if (i >= NT4) return;
    const float4 v = (i < NX4) ? ((const float4*)X)[i]
                               : ((const float4*)W)[i - NX4];
    __half2 lo = __floats2half2_rn(v.x, v.y);
    __half2 hi = __floats2half2_rn(v.z, v.w);
    uint2 o = make_uint2(*(uint32_t*)&lo, *(uint32_t*)&hi);
    if (i < NX4) ((uint2*)g_Xh)[i] = o;
    else         ((uint2*)g_Wh)[i - NX4] = o;
}

// ===========================================================================
// Phase 1: Xg[d, r, :] = X[r,:] @ W[d]^T + Wb[d] + Rb[d]
// fp16 mma.sync.m16n8k16, cp.async double-buffered fp16 tiles.
// Block tile 128x128, 8 warps (4m x 2n), warp tile 32x64, K-chunk 32.
// ===========================================================================
#define PSTR 40

__global__ __launch_bounds__(256) void gemm_xw_fp16(const float* __restrict__ Bb) {
    __shared__ __half As[2][128][PSTR];
    __shared__ __half Bs[2][128][PSTR];
    __shared__ float biass[128];

    const int tid  = threadIdx.x;
    const int wid  = tid >> 5, lane = tid & 31;
    const int d    = blockIdx.z;
    const int col0 = blockIdx.x * 128;
    const int row0 = blockIdx.y * 128;
    const __half* Am = g_Xh + (size_t)row0 * ID;
    const __half* Bm = g_Wh + ((size_t)d * NG + col0) * ID;
    float* C = g_Xg + (size_t)d * SLEN * BSZ * NG;

    if (blockIdx.x == 0 && blockIdx.y == 0 && blockIdx.z == 0 && tid == 0) {
        g_barD[0] = 0u;
        g_barD[1] = 0u;
    }

    if (tid < 128) {
        biass[tid] = Bb[(size_t)d * 4096 + col0 + tid]
                   + Bb[(size_t)d * 4096 + 2048 + col0 + tid];
    }

    const int wm  = (wid & 3) * 32;
    const int wn  = (wid >> 2) * 64;
    const int grp = lane >> 2;
    const int thr = lane & 3;

    const int aM  = lane & 15;
    const int aK8 = (lane >> 4) << 3;

    // cp.async fill mapping: idx = tid + it*256; r = idx>>2, seg = idx&3 (8 halves)
    const int fr0 = tid >> 2, fseg = (tid & 3) * 8;

    float cr[2][8][4];
#pragma unroll
    for (int mt = 0; mt < 2; mt++)
#pragma unroll
        for (int nt = 0; nt < 8; nt++)
#pragma unroll
            for (int q = 0; q < 4; q++) cr[mt][nt][q] = 0.f;

    // Prologue: issue chunk 0 into buffer 0
    {
#pragma unroll
        for (int it = 0; it < 2; it++) {
            int r = fr0 + it * 64;
            uint32_t da = smem_u32(&As[0][r][fseg]);
            uint32_t db = smem_u32(&Bs[0][r][fseg]);
            asm volatile("cp.async.cg.shared.global [%0], [%1], 16;"
                         :: "r"(da), "l"(Am + (size_t)r * ID + fseg));
            asm volatile("cp.async.cg.shared.global [%0], [%1], 16;"
                         :: "r"(db), "l"(Bm + (size_t)r * ID + fseg));
        }
        asm volatile("cp.async.commit_group;");
    }

#pragma unroll 1
    for (int c = 0; c < 16; c++) {
        if (c < 15) {
            const int kk = (c + 1) * 32;
            const int nb = (c + 1) & 1;
#pragma unroll
            for (int it = 0; it < 2; it++) {
                int r = fr0 + it * 64;
                uint32_t da = smem_u32(&As[nb][r][fseg]);
                uint32_t db = smem_u32(&Bs[nb][r][fseg]);
                asm volatile("cp.async.cg.shared.global [%0], [%1], 16;"
                             :: "r"(da), "l"(Am + (size_t)r * ID + kk + fseg));
                asm volatile("cp.async.cg.shared.global [%0], [%1], 16;"
                             :: "r"(db), "l"(Bm + (size_t)r * ID + kk + fseg));
            }
            asm volatile("cp.async.commit_group;");
            asm volatile("cp.async.wait_group 1;");
        } else {
            asm volatile("cp.async.wait_group 0;");
        }
        __syncthreads();

        const int cb = c & 1;
#pragma unroll
        for (int ks = 0; ks < 2; ks++) {
            const int k0 = ks * 16;
            uint32_t af[2][4];
#pragma unroll
            for (int mt = 0; mt < 2; mt++) {
                uint32_t addr = smem_u32(&As[cb][wm + mt * 16 + aM][k0 + aK8]);
                asm volatile(
                    "ldmatrix.sync.aligned.m8n8.x4.shared.b16 {%0,%1,%2,%3}, [%4];"
                    : "=r"(af[mt][0]), "=r"(af[mt][1]), "=r"(af[mt][2]), "=r"(af[mt][3])
                    : "r"(addr));
            }
#pragma unroll
            for (int nt16 = 0; nt16 < 4; nt16++) {
                uint32_t r0, r1, r2, r3;
                uint32_t addr = smem_u32(&Bs[cb][wn + nt16 * 16 + aM][k0 + aK8]);
                asm volatile(
                    "ldmatrix.sync.aligned.m8n8.x4.shared.b16 {%0,%1,%2,%3}, [%4];"
                    : "=r"(r0), "=r"(r1), "=r"(r2), "=r"(r3) : "r"(addr));
#pragma unroll
                for (int mt = 0; mt < 2; mt++) {
                    asm volatile(
                        "mma.sync.aligned.m16n8k16.row.col.f32.f16.f16.f32 "
                        "{%0,%1,%2,%3}, {%4,%5,%6,%7}, {%8,%9}, {%0,%1,%2,%3};"
                        : "+f"(cr[mt][2 * nt16][0]), "+f"(cr[mt][2 * nt16][1]),
                          "+f"(cr[mt][2 * nt16][2]), "+f"(cr[mt][2 * nt16][3])
                        : "r"(af[mt][0]), "r"(af[mt][1]), "r"(af[mt][2]), "r"(af[mt][3]),
                          "r"(r0), "r"(r2));
                    asm volatile(
                        "mma.sync.aligned.m16n8k16.row.col.f32.f16.f16.f32 "
                        "{%0,%1,%2,%3}, {%4,%5,%6,%7}, {%8,%9}, {%0,%1,%2,%3};"
                        : "+f"(cr[mt][2 * nt16 + 1][0]), "+f"(cr[mt][2 * nt16 + 1][1]),
                          "+f"(cr[mt][2 * nt16 + 1][2]), "+f"(cr[mt][2 * nt16 + 1][3])
                        : "r"(af[mt][0]), "r"(af[mt][1]), "r"(af[mt][2]), "r"(af[mt][3]),
                          "r"(r1), "r"(r3));
                }
            }
        }
        __syncthreads();   // protect buffer reuse (WAR) before next issue
    }

#pragma unroll
    for (int mt = 0; mt < 2; mt++) {
        const int m0 = row0 + wm + mt * 16 + grp;
#pragma unroll
        for (int nt = 0; nt < 8; nt++) {
            const int cl = wn + nt * 8 + 2 * thr;
            float2 v0 = make_float2(cr[mt][nt][0] + biass[cl],
                                    cr[mt][nt][1] + biass[cl + 1]);
            float2 v1 = make_float2(cr[mt][nt][2] + biass[cl],
                                    cr[mt][nt][3] + biass[cl + 1]);
            *(float2*)(C + (size_t)m0 * NG + col0 + cl)       = v0;
            *(float2*)(C + (size_t)(m0 + 8) * NG + col0 + cl) = v1;
        }
    }
}

// ===========================================================================
// Phase 2: persistent bidirectional recurrence, fp16 mma.m16n8k16.
// Per-direction grid barrier via red.release (no membar on critical path).
// ===========================================================================
__device__ __forceinline__ void grid_barrier(unsigned* ctr, unsigned target) {
    __syncthreads();
    if (threadIdx.x == 0) {
        asm volatile("red.release.gpu.global.add.u32 [%0], 1;"
                     :: "l"(ctr) : "memory");
        unsigned v;
        do {
            asm volatile("ld.acquire.gpu.u32 %0, [%1];" : "=r"(v) : "l"(ctr) : "memory");
        } while (v < target);
    }
    __syncthreads();
}

__device__ __forceinline__ float sigmoidf_(float x) {
    return 1.f / (1.f + __expf(-x));
}
__device__ __forceinline__ float tanhf_(float x) {
    float ax = fabsf(x);
    float e  = __expf(-2.f * ax);
    float r  = (1.f - e) / (1.f + e);
    return copysignf(r, x);
}

#define HS_BYTES  (512 * HS_STRIDE * 2)

__global__ __launch_bounds__(512, 1) void lstm_rec(const float* __restrict__ R,
                                                   const int*   __restrict__ seq,
                                                   const float* __restrict__ h0,
                                                   const float* __restrict__ c0,
                                                   const float* __restrict__ P,
                                                   float* __restrict__ out) {
    extern __shared__ __half hs[];           // [512][HS_STRIDE] fp16 h
    __shared__ float accs[4][4][8][65];      // [kg][gate][hl][b]
    __shared__ float xgs[4][64][9];          // [gate][b][hl]
    __shared__ float cs[8][64], c0s[8][64], h0s[8][64];
    __shared__ float Ps[3][8];
    __shared__ int   slen[BSZ];

    const int blk = blockIdx.x;
    const int d   = blk >> 6;
    const int hb  = (blk & 63) * 8;
    const int tid = threadIdx.x;
    const int wid = tid >> 5, lane = tid & 31;
    const int grp = lane >> 2, thr = lane & 3;
    const int mg  = wid & 1;
    const int ng  = (wid >> 1) & 1;
    const int kg  = wid >> 2;
    const int m0  = mg * 32;
    const int kb0 = kg * 128;

    unsigned* bar = &g_barD[d];
    const uint32_t hs_b = smem_u32(hs);

    const int seg   = lane >> 3;
    const int laneK = ((seg >> 1) << 3) + (lane & 7);
    const int laneM = (seg & 1) << 3;

    uint32_t Rlo[2][8], Rhi[2][8];
#pragma unroll
    for (int nt2 = 0; nt2 < 2; nt2++) {
        const float* Rrow = R + ((size_t)d * NG + (2 * ng + nt2) * 512 + hb + grp) * HID + kb0;
#pragma unroll
        for (int ks = 0; ks < 8; ks++) {
            const int k = ks * 16;
            __half2 lo = __floats2half2_rn(Rrow[k + 2 * thr], Rrow[k + 2 * thr + 1]);
            __half2 hi = __floats2half2_rn(Rrow[k + 2 * thr + 8], Rrow[k + 2 * thr + 9]);
            Rlo[nt2][ks] = *(uint32_t*)&lo;
            Rhi[nt2][ks] = *(uint32_t*)&hi;
        }
    }

    if (tid < BSZ) slen[tid] = seq[tid];
    if (tid < 24) {
        int w = tid / 8, hl = tid % 8;
        Ps[w][hl] = P[(size_t)d * 1536 + w * 512 + hb + hl];
    }
    {
        int hl = tid >> 6, b = tid & 63;
        size_t idx = ((size_t)d * BSZ + b) * HID + hb + hl;
        float hv = h0[idx], cv = c0[idx];
        h0s[hl][b] = hv; c0s[hl][b] = cv; cs[hl][b] = cv;
        g_h[0][d][hb + hl][b] = __float2half(hv);
    }

    unsigned target = NBLKD;
    grid_barrier(bar, target); target += NBLKD;

    float* Yh = out + 33554432;
    float* Yc = Yh + 65536;

    const int xb = tid >> 3, xq = tid & 7;
    const int xgate = xq >> 1, xh4 = (xq & 1) * 4;

    const int sgrp   = tid >> 7;
    const int slocal = tid & 127;

    for (int s = 0; s < SLEN; ++s) {
        const int t   = d ? (SLEN - 1 - s) : s;
        const int cur = s & 1, nxt = cur ^ 1;

        const float* xp = g_Xg + (((size_t)d * SLEN + t) * BSZ + xb) * NG
                        + xgate * 512 + hb + xh4;
        float4 xv = *(const float4*)xp;

        grid_barrier(bar, target); target += NBLKD;

        xgs[xgate][xb][xh4 + 0] = xv.x;
        xgs[xgate][xb][xh4 + 1] = xv.y;
        xgs[xgate][xb][xh4 + 2] = xv.z;
        xgs[xgate][xb][xh4 + 3] = xv.w;

        // Stage own k-quarter in 2 commit groups
        {
            const char* src = (const char*)&g_h[cur][d][sgrp * 128][0];
            uint32_t    dst = hs_b + (uint32_t)sgrp * CHUNK_BYTES;
#pragma unroll
            for (int i = 0; i < 5; i++) {
                uint32_t off = (uint32_t)(slocal + i * 128) * 16;
                asm volatile("cp.async.cg.shared.global [%0], [%1], 16;"
                             :: "r"(dst + off), "l"(src + off));
            }
            asm volatile("cp.async.commit_group;");
#pragma unroll
            for (int i = 5; i < 9; i++) {
                uint32_t off = (uint32_t)(slocal + i * 128) * 16;
                asm volatile("cp.async.cg.shared.global [%0], [%1], 16;"
                             :: "r"(dst + off), "l"(src + off));
            }
            asm volatile("cp.async.commit_group;");
        }

        float acc[2][2][4];
#pragma unroll
        for (int mtf = 0; mtf < 2; mtf++)
#pragma unroll
            for (int nt2 = 0; nt2 < 2; nt2++)
#pragma unroll
                for (int q = 0; q < 4; q++) acc[mtf][nt2][q] = 0.f;

        asm volatile("cp.async.wait_group 1;");
        asm volatile("bar.sync %0, 128;" :: "r"(1 + sgrp) : "memory");

#pragma unroll
        for (int ks = 0; ks < 4; ks++) {
            const int kb = kb0 + ks * 16 + laneK;
#pragma unroll
            for (int mtf = 0; mtf < 2; mtf++) {
                const int mb = m0 + mtf * 16 + laneM;
                uint32_t addr = hs_b + (uint32_t)(kb * HS_STRIDE + mb) * 2;
                uint32_t a0, a1, a2, a3;
                asm volatile(
                    "ldmatrix.sync.aligned.m8n8.x4.trans.shared.b16 {%0,%1,%2,%3}, [%4];"
                    : "=r"(a0), "=r"(a1), "=r"(a2), "=r"(a3) : "r"(addr));
#pragma unroll
                for (int nt2 = 0; nt2 < 2; nt2++) {
                    asm volatile(
                        "mma.sync.aligned.m16n8k16.row.col.f32.f16.f16.f32 "
                        "{%0,%1,%2,%3}, {%4,%5,%6,%7}, {%8,%9}, {%0,%1,%2,%3};"
                        : "+f"(acc[mtf][nt2][0]), "+f"(acc[mtf][nt2][1]),
                          "+f"(acc[mtf][nt2][2]), "+f"(acc[mtf][nt2][3])
                        : "r"(a0), "r"(a1), "r"(a2), "r"(a3),
                          "r"(Rlo[nt2][ks]), "r"(Rhi[nt2][ks]));
                }
            }
        }

        asm volatile("cp.async.wait_group 0;");
        asm volatile("bar.sync %0, 128;" :: "r"(1 + sgrp) : "memory");

#pragma unroll
        for (int ks = 4; ks < 8; ks++) {
            const int kb = kb0 + ks * 16 + laneK;
#pragma unroll
            for (int mtf = 0; mtf < 2; mtf++) {
                const int mb = m0 + mtf * 16 + laneM;
                uint32_t addr = hs_b + (uint32_t)(kb * HS_STRIDE + mb) * 2;
                uint32_t a0, a1, a2, a3;
                asm volatile(
                    "ldmatrix.sync.aligned.m8n8.x4.trans.shared.b16 {%0,%1,%2,%3}, [%4];"
                    : "=r"(a0), "=r"(a1), "=r"(a2), "=r"(a3) : "r"(addr));
#pragma unroll
                for (int nt2 = 0; nt2 < 2; nt2++) {
                    asm volatile(
                        "mma.sync.aligned.m16n8k16.row.col.f32.f16.f16.f32 "
                        "{%0,%1,%2,%3}, {%4,%5,%6,%7}, {%8,%9}, {%0,%1,%2,%3};"
                        : "+f"(acc[mtf][nt2][0]), "+f"(acc[mtf][nt2][1]),
                          "+f"(acc[mtf][nt2][2]), "+f"(acc[mtf][nt2][3])
                        : "r"(a0), "r"(a1), "r"(a2), "r"(a3),
                          "r"(Rlo[nt2][ks]), "r"(Rhi[nt2][ks]));
                }
            }
        }

#pragma unroll
        for (int mtf = 0; mtf < 2; mtf++) {
            const int m = m0 + mtf * 16 + grp;
#pragma unroll
            for (int nt2 = 0; nt2 < 2; nt2++) {
                const int g = 2 * ng + nt2;
                accs[kg][g][2 * thr]    [m]     = acc[mtf][nt2][0];
                accs[kg][g][2 * thr + 1][m]     = acc[mtf][nt2][1];
                accs[kg][g][2 * thr]    [m + 8] = acc[mtf][nt2][2];
                accs[kg][g][2 * thr + 1][m + 8] = acc[mtf][nt2][3];
            }
        }
        __syncthreads();

        {
            int hl = tid >> 6, b = tid & 63;
            float gi = accs[0][0][hl][b] + accs[1][0][hl][b]
                     + accs[2][0][hl][b] + accs[3][0][hl][b] + xgs[0][b][hl];
            float go = accs[0][1][hl][b] + accs[1][1][hl][b]
                     + accs[2][1][hl][b] + accs[3][1][hl][b] + xgs[1][b][hl];
            float gf = accs[0][2][hl][b] + accs[1][2][hl][b]
                     + accs[2][2][hl][b] + accs[3][2][hl][b] + xgs[2][b][hl];
            float gg = accs[0][3][hl][b] + accs[1][3][hl][b]
                     + accs[2][3][hl][b] + accs[3][3][hl][b] + xgs[3][b][hl];
            float c  = cs[hl][b];
            float iv = sigmoidf_(gi + Ps[0][hl] * c);
            float fv = sigmoidf_(gf + Ps[1][hl] * c);
            float ct = tanhf_(gg);
            float cn = fv * c + iv * ct;
            float ov = sigmoidf_(go + Ps[2][hl] * cn);
            float hn = ov * tanhf_(cn);
            if (t >= slen[b]) { hn = h0s[hl][b]; cn = c0s[hl][b]; }
            cs[hl][b] = cn;
            g_h[nxt][d][hb + hl][b] = __float2half(hn);
            out[(((size_t)t * 2 + d) * BSZ + b) * HID + hb + hl] = hn;
            if (s == SLEN - 1) {
                size_t fi = ((size_t)d * BSZ + b) * HID + hb + hl;
                Yh[fi] = hn;
                Yc[fi] = cn;
            }
        }
    }
}

// ---------------------------------------------------------------------------
extern "C" void kernel_launch(void* const* d_in, const int* in_sizes, int n_in,
                              void* d_out, int out_size) {
    const float* X   = (const float*)d_in[0];
    const float* W   = (const float*)d_in[1];
    const float* R   = (const float*)d_in[2];
    const float* Bb  = (const float*)d_in[3];
    const int*   sl  = (const int*)  d_in[4];
    const float* h0  = (const float*)d_in[5];
    const float* c0  = (const float*)d_in[6];
    const float* P   = (const float*)d_in[7];
    float* out = (float*)d_out;

    static int configured = 0;
    if (!configured) {
        cudaFuncSetAttribute(lstm_rec, cudaFuncAttributeMaxDynamicSharedMemorySize,
                             HS_BYTES);
        configured = 1;
    }

    convert_fp16<<<(NT4 + 255) / 256, 256>>>(X, W);
    gemm_xw_fp16<<<dim3(16, 256, 2), 256>>>(Bb);
    lstm_rec<<<NBLK, 512, HS_BYTES>>>(R, sl, h0, c0, P, out);
}